// round 9
// baseline (speedup 1.0000x reference)
#include <cuda_runtime.h>
#include <cstdint>

// Problem constants (fixed by the reference)
#define HDIM 128
#define WDIM 128
#define DDIM 8
#define CDIM 64
#define NROI 80          // B(16) * 5 keypoints
#define CS   16.0f       // crop half-size = H * 1/8
#define FP   36          // max footprint (rows/cols) per ROI: 2*CS + slack

__global__ __launch_bounds__(256, 8)
void roi_align_25d_kernel(const float* __restrict__ fea,
                          const float* __restrict__ kp,
                          float* __restrict__ out)
{
    const int c   = blockIdx.x;          // 0..63
    const int roi = blockIdx.y;          // 0..79
    const int b   = roi / 5;
    const int tid = threadIdx.x;

    __shared__ float Wy[2][FP];
    __shared__ float Wx[2][FP];
    __shared__ float tmp[2][FP * DDIM];  // pass-1 result: (ph, xi*8+d)

    // ---- per-ROI scalar params (computed redundantly; cheap) ----
    const float kx   = kp[roi * 3 + 0] * (float)WDIM;
    const float ky   = kp[roi * 3 + 1] * (float)HDIM;
    const float xmin = fminf(fmaxf(kx - CS, 0.0f), (float)WDIM - 1.0f);
    const float xmax = fminf(fmaxf(kx + CS, 0.0f), (float)WDIM - 1.0f);
    const float ymin = fminf(fmaxf(ky - CS, 0.0f), (float)HDIM - 1.0f);
    const float ymax = fminf(fmaxf(ky + CS, 0.0f), (float)HDIM - 1.0f);
    const float roi_w = fmaxf(xmax - xmin, 1.0f);
    const float roi_h = fmaxf(ymax - ymin, 1.0f);
    const float bin_w = roi_w * 0.5f;    // PW = 2
    const float bin_h = roi_h * 0.5f;    // PH = 2
    const int   gw    = (int)ceilf(roi_w * 0.5f);   // 1..16
    const int   gh    = (int)ceilf(roi_h * 0.5f);   // 1..16
    const int   base_y = (int)floorf(ymin);
    const int   base_x = (int)floorf(xmin);
    // sample coords are strictly < min + roi_{h,w}; indices used are
    // [base, min(size-1, floor(min+roi)+1)]
    const int   cnt_y = min(HDIM - 1, (int)floorf(ymin + roi_h) + 1) - base_y + 1;
    const int   cnt_x = min(WDIM - 1, (int)floorf(xmin + roi_w) + 1) - base_x + 1;
    const float inv_count = 1.0f / (float)(gh * gw);

    // ---- zero weight arrays ----
    if (tid < 2 * FP) {
        (&Wy[0][0])[tid] = 0.0f;
        (&Wx[0][0])[tid] = 0.0f;
    }
    __syncthreads();

    // ---- build separable per-axis weights (thread = (axis, ph, g) sample) ----
    if (tid < 64) {
        const bool isx  = (tid >= 32);
        const int  ph   = (tid & 31) >> 4;     // 0..1
        const int  g    = tid & 15;            // 0..15
        const int  gcnt = isx ? gw : gh;
        if (g < gcnt) {
            const float mn   = isx ? xmin  : ymin;
            const float bn   = isx ? bin_w : bin_h;
            const int   size = isx ? WDIM  : HDIM;
            const int   base = isx ? base_x : base_y;
            // coord >= mn >= 0 always (mn clipped into [0, size-1])
            const float coord = mn + (float)ph * bn
                              + ((float)g + 0.5f) * (bn / (float)gcnt);
            const int l0 = (int)floorf(coord);
            int lo, hi; float frac;
            if (l0 >= size - 1) { lo = size - 1; hi = size - 1; frac = 0.0f; }
            else                { lo = l0;       hi = l0 + 1;   frac = coord - (float)l0; }
            float* Wp = isx ? &Wx[ph][0] : &Wy[ph][0];
            atomicAdd(&Wp[lo - base], 1.0f - frac);
            atomicAdd(&Wp[hi - base], frac);
        }
    }
    __syncthreads();

    // ---- pass 1: reduce over y with float2 loads. unit = pair (xi*8+d)/2 ----
    const int npairs = cnt_x * (DDIM / 2);           // <= 34*4 = 136 <= 256
    const float* fptr = fea +
        ((((size_t)(b * CDIM + c)) * HDIM + base_y) * WDIM + base_x) * DDIM;

    if (tid < npairs) {
        const float2* p = (const float2*)fptr + tid;  // fptr is 32B-aligned
        float a0x = 0.0f, a0y = 0.0f, a1x = 0.0f, a1y = 0.0f;
        #pragma unroll 8
        for (int yi = 0; yi < cnt_y; yi++) {
            const float2 v  = p[(size_t)yi * (WDIM * DDIM / 2)];
            const float  w0 = Wy[0][yi];
            const float  w1 = Wy[1][yi];
            a0x += w0 * v.x;  a0y += w0 * v.y;
            a1x += w1 * v.x;  a1y += w1 * v.y;
        }
        tmp[0][2 * tid]     = a0x;
        tmp[0][2 * tid + 1] = a0y;
        tmp[1][2 * tid]     = a1x;
        tmp[1][2 * tid + 1] = a1y;
    }
    __syncthreads();

    // ---- pass 2: reduce over x, write 2x2x8 outputs ----
    if (tid < 32) {
        const int di = tid & 7;
        const int pw = (tid >> 3) & 1;
        const int ph = tid >> 4;
        float acc = 0.0f;
        for (int xi = 0; xi < cnt_x; xi++)
            acc += Wx[pw][xi] * tmp[ph][xi * DDIM + di];
        acc *= inv_count;
        // out layout: (b, 5, c, PH, PW, D) -> ((roi*64 + c)*4 + ph*2 + pw)*8 + di
        out[((size_t)roi * CDIM + c) * 32 + ph * 16 + pw * 8 + di] = acc;
    }
}

extern "C" void kernel_launch(void* const* d_in, const int* in_sizes, int n_in,
                              void* d_out, int out_size)
{
    // Defensive input-order resolution: fea has 16*64*128*128*8 = 8,388,608
    // elements; keypoints has 16*5*3 = 240. Pick by size.
    int fi = 0, ki = 1;
    if (n_in >= 2 && in_sizes[0] < in_sizes[1]) { fi = 1; ki = 0; }
    const float* fea = (const float*)d_in[fi];
    const float* kp  = (const float*)d_in[ki];
    float* out       = (float*)d_out;           // (16,5,64,2,2,8) fp32

    dim3 grid(CDIM, NROI);   // (c, roi) = 64 x 80 = 5120 blocks
    roi_align_25d_kernel<<<grid, 256>>>(fea, kp, out);
}